// round 16
// baseline (speedup 1.0000x reference)
#include <cuda_runtime.h>

// hidden_states: [B=32, S=4096, H=768] fp32
// w_start, w_end: [768] fp32
// out: [2, B*S] fp32  (start_logits then end_logits)
//
// Software-pipeline depth 1: consume batch k (frees h via WAR), issue batch
// k+1's 12 LDG.128, THEN do the reduction/store tail — overlapping the tail
// (10 SHFL + stores, ~300 cyc of zero memory pressure) with the next batch's
// DRAM latency. Persistent grid keeps the pipeline warm.
// (R15 fix: redux.sync.f32 doesn't exist on sm_103 — SHFL butterfly.)

static constexpr int H   = 768;
static constexpr int HV  = H / 4;      // 192 float4 per row
static constexpr int VPL = HV / 32;    // 6 float4 per lane per row
static constexpr int R   = 2;          // rows per warp per iteration
static constexpr int THREADS = 256;    // 8 warps/block
static constexpr int BLOCKS = 3 * 148; // 3 blocks/SM resident

__global__ __launch_bounds__(THREADS, 3)   // ~84-reg budget
void dual_dot_kernel(const float4* __restrict__ hs,
                     const float4* __restrict__ ws,
                     const float4* __restrict__ we,
                     float* __restrict__ out,
                     int rows, int stride_rows) {
    __shared__ float4 sa[HV];
    __shared__ float4 sb[HV];
    for (int i = threadIdx.x; i < HV; i += THREADS) {
        sa[i] = ws[i];
        sb[i] = we[i];
    }
    __syncthreads();

    const int gw   = (int)(blockIdx.x * (THREADS / 32) + (threadIdx.x >> 5));
    const int lane = threadIdx.x & 31;

    int row0 = gw * R;
    if (row0 >= rows) return;

    float4 h[R][VPL];

    // Prologue: front-batch the first pair's 12 LDG.128.
    {
        const float4* p = hs + (size_t)row0 * HV;
        #pragma unroll
        for (int j = 0; j < VPL; ++j)
            #pragma unroll
            for (int r = 0; r < R; ++r)
                h[r][j] = __ldcs(&p[(size_t)r * HV + lane + 32 * j]);
    }

    while (true) {
        // 1) Consume batch into accumulators (this is the scoreboard wait).
        float s[R], e[R];
        #pragma unroll
        for (int r = 0; r < R; ++r) { s[r] = 0.0f; e[r] = 0.0f; }

        #pragma unroll
        for (int j = 0; j < VPL; ++j) {
            const int idx = lane + 32 * j;
            float4 a = sa[idx];
            float4 b = sb[idx];
            #pragma unroll
            for (int r = 0; r < R; ++r) {
                s[r] = fmaf(h[r][j].x, a.x, s[r]);
                s[r] = fmaf(h[r][j].y, a.y, s[r]);
                s[r] = fmaf(h[r][j].z, a.z, s[r]);
                s[r] = fmaf(h[r][j].w, a.w, s[r]);
                e[r] = fmaf(h[r][j].x, b.x, e[r]);
                e[r] = fmaf(h[r][j].y, b.y, e[r]);
                e[r] = fmaf(h[r][j].z, b.z, e[r]);
                e[r] = fmaf(h[r][j].w, b.w, e[r]);
            }
        }

        // 2) h is dead now — issue the NEXT pair's loads before the tail.
        const int rnext = row0 + stride_rows;
        if (rnext < rows) {
            const float4* p = hs + (size_t)rnext * HV;
            #pragma unroll
            for (int j = 0; j < VPL; ++j)
                #pragma unroll
                for (int r = 0; r < R; ++r)
                    h[r][j] = __ldcs(&p[(size_t)r * HV + lane + 32 * j]);
        }

        // 3) Reduction + store tail overlaps the in-flight next batch.
        #pragma unroll
        for (int r = 0; r < R; ++r) {
            #pragma unroll
            for (int o = 16; o > 0; o >>= 1) {
                s[r] += __shfl_xor_sync(0xffffffffu, s[r], o);
                e[r] += __shfl_xor_sync(0xffffffffu, e[r], o);
            }
        }
        if (lane == 0) {
            #pragma unroll
            for (int r = 0; r < R; ++r) {
                out[row0 + r]        = s[r];   // start_logits
                out[rows + row0 + r] = e[r];   // end_logits
            }
        }

        if (rnext >= rows) break;
        row0 = rnext;
    }
}

extern "C" void kernel_launch(void* const* d_in, const int* in_sizes, int n_in,
                              void* d_out, int out_size) {
    const float4* hs = (const float4*)d_in[0];
    const float4* ws = (const float4*)d_in[1];
    const float4* we = (const float4*)d_in[2];
    float* out       = (float*)d_out;

    const int rows = in_sizes[0] / H;                 // 131072
    const int total_warps = BLOCKS * (THREADS / 32);  // 3552
    const int stride_rows = total_warps * R;          // 7104

    dual_dot_kernel<<<BLOCKS, THREADS>>>(hs, ws, we, out, rows, stride_rows);
}

// round 17
// speedup vs baseline: 1.0644x; 1.0644x over previous
#include <cuda_runtime.h>

// hidden_states: [B=32, S=4096, H=768] fp32
// w_start, w_end: [768] fp32
// out: [2, B*S] fp32  (start_logits then end_logits)
//
// FINAL (= R9, best measured 59.8us): front-batched 12x LDG.128 per warp
// (j-outer interleave over 2 rows), natural register allocation (regs=40,
// occ ~64%). Knob map proven: DRAM saturates ~84-85% for any config with
// sufficient MLP; within the plateau dur tracks occupancy. Deeper batches
// (R=4), cp.async pipelines, explicit SW pipelining, and persistent grids
// all measured slower — warp-level round-robin is the best latency hider.

static constexpr int H   = 768;
static constexpr int HV  = H / 4;      // 192 float4 per row
static constexpr int VPL = HV / 32;    // 6 float4 per lane per row
static constexpr int R   = 2;          // rows per warp
static constexpr int THREADS = 256;    // 8 warps/block

__global__ __launch_bounds__(THREADS)
void dual_dot_kernel(const float4* __restrict__ hs,
                     const float4* __restrict__ ws,
                     const float4* __restrict__ we,
                     float* __restrict__ out,
                     int rows) {
    // Weights in shared memory: 2 x 192 float4 = 6 KB, conflict-free lane-indexed reads.
    __shared__ float4 sa[HV];
    __shared__ float4 sb[HV];
    for (int i = threadIdx.x; i < HV; i += THREADS) {
        sa[i] = ws[i];
        sb[i] = we[i];
    }
    __syncthreads();

    const int warp = (int)((blockIdx.x * blockDim.x + threadIdx.x) >> 5);
    const int lane = threadIdx.x & 31;
    const int row0 = warp * R;
    if (row0 >= rows) return;

    const float4* __restrict__ p = hs + (size_t)row0 * HV;

    float s[R], e[R];
    #pragma unroll
    for (int r = 0; r < R; ++r) { s[r] = 0.0f; e[r] = 0.0f; }

    // Front-batch all R*VPL = 12 independent LDG.128s, then consume.
    float4 h[R][VPL];
    #pragma unroll
    for (int j = 0; j < VPL; ++j) {
        #pragma unroll
        for (int r = 0; r < R; ++r) {
            h[r][j] = __ldcs(&p[(size_t)r * HV + lane + 32 * j]);
        }
    }

    #pragma unroll
    for (int j = 0; j < VPL; ++j) {
        const int idx = lane + 32 * j;
        float4 a = sa[idx];
        float4 b = sb[idx];
        #pragma unroll
        for (int r = 0; r < R; ++r) {
            s[r] = fmaf(h[r][j].x, a.x, s[r]);
            s[r] = fmaf(h[r][j].y, a.y, s[r]);
            s[r] = fmaf(h[r][j].z, a.z, s[r]);
            s[r] = fmaf(h[r][j].w, a.w, s[r]);
            e[r] = fmaf(h[r][j].x, b.x, e[r]);
            e[r] = fmaf(h[r][j].y, b.y, e[r]);
            e[r] = fmaf(h[r][j].z, b.z, e[r]);
            e[r] = fmaf(h[r][j].w, b.w, e[r]);
        }
    }

    #pragma unroll
    for (int r = 0; r < R; ++r) {
        #pragma unroll
        for (int o = 16; o > 0; o >>= 1) {
            s[r] += __shfl_xor_sync(0xffffffffu, s[r], o);
            e[r] += __shfl_xor_sync(0xffffffffu, e[r], o);
        }
    }

    if (lane == 0) {
        #pragma unroll
        for (int r = 0; r < R; ++r) {
            out[row0 + r]        = s[r];   // start_logits
            out[rows + row0 + r] = e[r];   // end_logits
        }
    }
}

extern "C" void kernel_launch(void* const* d_in, const int* in_sizes, int n_in,
                              void* d_out, int out_size) {
    const float4* hs = (const float4*)d_in[0];
    const float4* ws = (const float4*)d_in[1];
    const float4* we = (const float4*)d_in[2];
    float* out       = (float*)d_out;

    const int rows = in_sizes[0] / H;                     // 131072
    const int rows_per_block = (THREADS / 32) * R;        // 16
    const int blocks = (rows + rows_per_block - 1) / rows_per_block;

    dual_dot_kernel<<<blocks, THREADS>>>(hs, ws, we, out, rows);
}